// round 2
// baseline (speedup 1.0000x reference)
#include <cuda_runtime.h>
#include <math.h>

#define B 64
#define C0 8
#define HW0 3136
#define C1 16
#define HW1 324
#define C2 32
#define F 10368
#define EPSN 1e-5f

// ---------------- persistent scratch ----------------
__device__ float g_h0[B*C0*HW0];
__device__ float g_a0[B*C0], g_b0[B*C0];
__device__ float g_h1[B*C1*HW1];
__device__ float g_a1[B*C1], g_b1[B*C1];
__device__ float g_h2[B*C2*HW1];
__device__ float g_a2[B*C2], g_b2[B*C2];
__device__ float g_bnsc[F], g_bnsh[F];
__device__ float g_part[81*B*32];
__device__ float g_y[B*32];

__device__ __forceinline__ float blockReduceSum(float v, volatile float* sh) {
    int lane = threadIdx.x & 31, wid = threadIdx.x >> 5;
#pragma unroll
    for (int o = 16; o > 0; o >>= 1) v += __shfl_down_sync(0xffffffffu, v, o);
    if (lane == 0) sh[wid] = v;
    __syncthreads();
    int nw = (blockDim.x + 31) >> 5;
    v = (threadIdx.x < (unsigned)nw) ? sh[threadIdx.x] : 0.f;
    if (wid == 0) {
#pragma unroll
        for (int o = 16; o > 0; o >>= 1) v += __shfl_down_sync(0xffffffffu, v, o);
    }
    __syncthreads();
    return v;  // valid in thread 0
}

// ---------------- K1: conv0 7x7 s4 p2 (phase-swizzled smem) ----------------
// grid 64x7 (8 output rows per tile), block 224. smem: in 3*35*4*57, w 1176.
__global__ void k_conv0(const float* __restrict__ x, const float* __restrict__ w,
                        const float* __restrict__ bias) {
    extern __shared__ float sm[];
    float* s_in = sm;            // 23940
    float* s_w  = sm + 23940;    // 1176
    int blk = blockIdx.x;
    int b = blk / 7, tile = blk - b * 7;
    int tid = threadIdx.x;

    for (int i = tid; i < 1176; i += 224) s_w[i] = w[i];

    const float* xb = x + (size_t)b * 3 * 224 * 224;
    for (int i = tid; i < 23835; i += 224) {
        int ic = i / 7945;
        int rem = i - ic * 7945;
        int r = rem / 227, sc = rem - r * 227;
        int gr = tile * 32 - 2 + r, gc = sc - 2;
        float v = 0.f;
        if (gr >= 0 && gr < 224 && gc >= 0 && gc < 224)
            v = xb[(ic * 224 + gr) * 224 + gc];
        s_in[((ic * 35 + r) * 4 + (sc & 3)) * 57 + (sc >> 2)] = v;
    }
    __syncthreads();

    int r0 = tid / 56, ocol = tid - r0 * 56;  // output rows {r0, r0+4} of tile
    float acc0[8], acc1[8];
#pragma unroll
    for (int o = 0; o < 8; o++) { acc0[o] = 0.f; acc1[o] = 0.f; }

    for (int ic = 0; ic < 3; ic++)
        for (int ky = 0; ky < 7; ky++) {
            int rowbase = (ic * 35 + r0 * 4 + ky) * 4;
#pragma unroll
            for (int kx = 0; kx < 7; kx++) {
                int idx = (rowbase + (kx & 3)) * 57 + ocol + (kx >> 2);
                float v0 = s_in[idx];
                float v1 = s_in[idx + 16 * 4 * 57];
                const float* wp = s_w + (ic * 7 + ky) * 7 + kx;
#pragma unroll
                for (int o = 0; o < 8; o++) {
                    float wv = wp[o * 147];
                    acc0[o] = fmaf(v0, wv, acc0[o]);
                    acc1[o] = fmaf(v1, wv, acc1[o]);
                }
            }
        }
    int orow0 = tile * 8 + r0;
#pragma unroll
    for (int o = 0; o < 8; o++) {
        float bv = bias[o];
        g_h0[((b * 8 + o) * 56 + orow0) * 56 + ocol]     = acc0[o] + bv;
        g_h0[((b * 8 + o) * 56 + orow0 + 4) * 56 + ocol] = acc1[o] + bv;
    }
}

// ---------------- K2: GroupNorm stats -> folded affine ----------------
__global__ void k_stats0(const float* __restrict__ gw, const float* __restrict__ gb) {
    __shared__ float sred[32];
    int bc = blockIdx.x, c = bc & 7;
    const float* p = g_h0 + (size_t)bc * HW0;
    float s = 0.f, q = 0.f;
    for (int i = threadIdx.x; i < HW0; i += blockDim.x) {
        float v = p[i]; s += v; q = fmaf(v, v, q);
    }
    s = blockReduceSum(s, sred);
    q = blockReduceSum(q, sred);
    if (threadIdx.x == 0) {
        float mu = s * (1.f / 3136.f);
        float var = q * (1.f / 3136.f) - mu * mu;   // biased
        float a = rsqrtf(var + EPSN) * gw[c];
        g_a0[bc] = a;
        g_b0[bc] = gb[c] - mu * a;
    }
}

// ---------------- K3: conv1 5x5 s3 p1 on relu(a*h0+b) ----------------
// grid 128 = 64 b x 2 oc-halves, block 352. smem: 25088 + 1600 floats.
__global__ void k_conv1(const float* __restrict__ w, const float* __restrict__ bias) {
    extern __shared__ float sm[];
    float* s_in = sm;
    float* s_w  = sm + 25088;
    __shared__ float s_a[8], s_b[8];
    int b = blockIdx.x >> 1, ocb = (blockIdx.x & 1) * 8;
    int tid = threadIdx.x;

    if (tid < 8) { s_a[tid] = g_a0[b * 8 + tid]; s_b[tid] = g_b0[b * 8 + tid]; }
    for (int i = tid; i < 1600; i += blockDim.x) {
        int o = i / 200;
        s_w[i] = w[(ocb + o) * 200 + (i - o * 200)];
    }
    __syncthreads();

    const float* h0b = g_h0 + (size_t)b * 8 * HW0;
    for (int i = tid; i < 25088; i += blockDim.x) {
        int ic = i / 3136;
        int rem = i - ic * 3136;
        int rr = rem / 56, cc = rem - rr * 56;
        int gr = rr - 1, gc = cc - 1;
        float v = 0.f;
        if (gr >= 0 && gc >= 0)
            v = fmaxf(fmaf(h0b[ic * 3136 + gr * 56 + gc], s_a[ic], s_b[ic]), 0.f);
        s_in[i] = v;
    }
    __syncthreads();

    if (tid < 324) {
        int oy = tid / 18, ox = tid - oy * 18;
        float acc[8];
#pragma unroll
        for (int o = 0; o < 8; o++) acc[o] = 0.f;
        for (int ic = 0; ic < 8; ic++)
            for (int ky = 0; ky < 5; ky++) {
                const float* ip = s_in + (ic * 56 + oy * 3 + ky) * 56 + ox * 3;
                const float* wp = s_w + ic * 25 + ky * 5;
#pragma unroll
                for (int kx = 0; kx < 5; kx++) {
                    float v = ip[kx];
#pragma unroll
                    for (int o = 0; o < 8; o++)
                        acc[o] = fmaf(v, wp[o * 200 + kx], acc[o]);
                }
            }
#pragma unroll
        for (int o = 0; o < 8; o++)
            g_h1[(b * 16 + ocb + o) * HW1 + tid] = acc[o] + bias[ocb + o];
    }
}

// ---------------- K4/K6: entropy + instance-norm stats per (b,c) ----------------
__global__ void k_entstats(int which, int C, const float* __restrict__ nw,
                           const float* __restrict__ nb) {
    __shared__ float s_ch[324];
    __shared__ float s_e[26];
    __shared__ float sred[32];
    const float* h = which ? g_h2 : g_h1;
    float* ga = which ? g_a2 : g_a1;
    float* gb = which ? g_b2 : g_b1;
    int bc = blockIdx.x, c = bc % C;
    int tid = threadIdx.x;

    float s = 0.f, q = 0.f;
    for (int i = tid; i < 324; i += blockDim.x) {
        float v = h[(size_t)bc * 324 + i];
        s_ch[i] = v; s += v; q = fmaf(v, v, q);
    }
    if (tid < 26) {
        float pk = __fdiv_rn((float)tid, 25.0f);
        float pc = fminf(fmaxf(pk, 1e-5f), 1.0f - 1e-5f);
        s_e[tid] = -pk * logf(pc);
    }
    __syncthreads();
    s = blockReduceSum(s, sred);
    q = blockReduceSum(q, sred);

    float ep = 0.f;
    if (tid < 196) {
        int py = tid / 14, px = tid - py * 14;
        float v[25];
#pragma unroll
        for (int dy = 0; dy < 5; dy++)
#pragma unroll
            for (int dx = 0; dx < 5; dx++)
                v[dy * 5 + dx] = s_ch[(py + dy) * 18 + px + dx];
        float mn = v[0], mx = v[0];
#pragma unroll
        for (int i = 1; i < 25; i++) { mn = fminf(mn, v[i]); mx = fmaxf(mx, v[i]); }
        float rng = (mx > mn) ? (mx - mn) : 1.0f;
        unsigned long long lo = 0ull, hi = 0ull;
        int c24 = 0;
#pragma unroll
        for (int i = 0; i < 25; i++) {
            float t = __fdiv_rn(v[i] - mn, rng) * 25.0f;
            int bi = (int)floorf(t);
            bi = bi < 0 ? 0 : (bi > 24 ? 24 : bi);
            if (bi < 12)      lo += 1ull << (bi * 5);
            else if (bi < 24) hi += 1ull << ((bi - 12) * 5);
            else              c24++;
        }
#pragma unroll
        for (int k = 0; k < 12; k++) ep += s_e[(lo >> (k * 5)) & 31];
#pragma unroll
        for (int k = 0; k < 12; k++) ep += s_e[(hi >> (k * 5)) & 31];
        ep += s_e[c24];
    }
    ep = blockReduceSum(ep, sred);

    if (tid == 0) {
        float ent = ep * (1.0f / 196.0f);
        float mu = s * (1.0f / 324.0f);
        float var = (q * (1.0f / 324.0f) - mu * mu) * (324.0f / 323.0f);  // unbiased
        float a = rsqrtf(var + EPSN) * nw[c] * ent;
        ga[bc] = a;
        gb[bc] = nb[c] - mu * a;
    }
}

// ---------------- K5: conv2 3x3 s1 p1 on relu(a*h1+b) ----------------
// grid 128 = 64 b x 2 oc-halves (16 each), block 352. smem 6400+2304 floats.
__global__ void k_conv2(const float* __restrict__ w, const float* __restrict__ bias) {
    extern __shared__ float sm[];
    float* s_in = sm;
    float* s_w  = sm + 6400;
    __shared__ float s_a[16], s_b[16];
    int b = blockIdx.x >> 1, ocb = (blockIdx.x & 1) * 16;
    int tid = threadIdx.x;

    if (tid < 16) { s_a[tid] = g_a1[b * 16 + tid]; s_b[tid] = g_b1[b * 16 + tid]; }
    for (int i = tid; i < 2304; i += blockDim.x) {
        int o = i / 144;
        s_w[i] = w[(ocb + o) * 144 + (i - o * 144)];
    }
    __syncthreads();

    for (int i = tid; i < 6400; i += blockDim.x) {
        int ic = i / 400;
        int rem = i - ic * 400;
        int rr = rem / 20, cc = rem - rr * 20;
        int gr = rr - 1, gc = cc - 1;
        float v = 0.f;
        if (gr >= 0 && gr < 18 && gc >= 0 && gc < 18)
            v = fmaxf(fmaf(g_h1[(b * 16 + ic) * 324 + gr * 18 + gc], s_a[ic], s_b[ic]), 0.f);
        s_in[i] = v;
    }
    __syncthreads();

    if (tid < 324) {
        int oy = tid / 18, ox = tid - oy * 18;
        float acc[16];
#pragma unroll
        for (int o = 0; o < 16; o++) acc[o] = 0.f;
        for (int ic = 0; ic < 16; ic++)
#pragma unroll
            for (int ky = 0; ky < 3; ky++) {
                const float* ip = s_in + (ic * 20 + oy + ky) * 20 + ox;
                const float* wp = s_w + ic * 9 + ky * 3;
#pragma unroll
                for (int kx = 0; kx < 3; kx++) {
                    float v = ip[kx];
#pragma unroll
                    for (int o = 0; o < 16; o++)
                        acc[o] = fmaf(v, wp[o * 144 + kx], acc[o]);
                }
            }
#pragma unroll
        for (int o = 0; o < 16; o++)
            g_h2[(b * 32 + ocb + o) * 324 + tid] = acc[o] + bias[ocb + o];
    }
}

// ---------------- K7: BatchNorm1d stats (batch axis, biased) ----------------
__global__ void k_bnstats(const float* __restrict__ bng, const float* __restrict__ bnb) {
    int f = blockIdx.x * blockDim.x + threadIdx.x;
    if (f >= F) return;
    int c = f / 324;
    float s = 0.f, q = 0.f;
    for (int b = 0; b < B; b++) {
        float v = fmaxf(fmaf(g_h2[(size_t)b * F + f], g_a2[b * 32 + c], g_b2[b * 32 + c]), 0.f);
        s += v; q = fmaf(v, v, q);
    }
    float mu = s * (1.f / 64.f);
    float var = q * (1.f / 64.f) - mu * mu;
    float sc = bng[f] * rsqrtf(var + EPSN);
    g_bnsc[f] = sc;
    g_bnsh[f] = bnb[f] - mu * sc;
}

// ---------------- K8: split-K GEMM, partials (deterministic) ----------------
// 81 blocks x 128 features; block 256. smem 64*129 + 32*128 floats.
__global__ void k_gemm(const float* __restrict__ fw) {
    extern __shared__ float sm[];
    float* s_h = sm;
    float* s_w = sm + 64 * 129;
    int f0 = blockIdx.x * 128;
    int tid = threadIdx.x;

    for (int i = tid; i < 8192; i += 256) {
        int bb = i >> 7, k = i & 127;
        int f = f0 + k, c = f / 324;
        float v = fmaxf(fmaf(g_h2[(size_t)bb * F + f], g_a2[bb * 32 + c], g_b2[bb * 32 + c]), 0.f);
        s_h[bb * 129 + k] = fmaf(v, g_bnsc[f], g_bnsh[f]);
    }
    for (int i = tid; i < 4096; i += 256) {
        int j = i >> 7, k = i & 127;
        s_w[j * 128 + k] = fw[(size_t)j * F + f0 + k];
    }
    __syncthreads();

    int bb = tid & 63, jg = tid >> 6;  // 4 groups of 8 outputs
    float acc[8];
#pragma unroll
    for (int j = 0; j < 8; j++) acc[j] = 0.f;
    const float* hp = s_h + bb * 129;
    const float* wp = s_w + jg * 8 * 128;
    for (int k = 0; k < 128; k++) {
        float hv = hp[k];
#pragma unroll
        for (int j = 0; j < 8; j++) acc[j] = fmaf(hv, wp[j * 128 + k], acc[j]);
    }
#pragma unroll
    for (int j = 0; j < 8; j++)
        g_part[(size_t)blockIdx.x * 2048 + bb * 32 + jg * 8 + j] = acc[j];
}

// ---------------- K9: reduce partials + fc bias + relu ----------------
__global__ void k_fcreduce(const float* __restrict__ fcb) {
    int t = blockIdx.x * blockDim.x + threadIdx.x;
    if (t >= B * 32) return;
    float acc = 0.f;
    for (int p = 0; p < 81; p++) acc += g_part[(size_t)p * 2048 + t];
    g_y[t] = fmaxf(acc + fcb[t & 31], 0.f);
}

// ---------------- K10: heads + softmax ----------------
__global__ void k_heads(const float* __restrict__ sw, const float* __restrict__ sb,
                        const float* __restrict__ vw, const float* __restrict__ vb,
                        float* __restrict__ out) {
    int b = threadIdx.x;
    if (b >= B) return;
    float h[32];
#pragma unroll
    for (int j = 0; j < 32; j++) h[j] = g_y[b * 32 + j];

    float sl[5];
#pragma unroll
    for (int k = 0; k < 5; k++) {
        float a = sb[k];
        for (int j = 0; j < 32; j++) a = fmaf(h[j], sw[k * 32 + j], a);
        sl[k] = a;
    }
    float mx = sl[0];
#pragma unroll
    for (int k = 1; k < 5; k++) mx = fmaxf(mx, sl[k]);
    float den = 0.f;
#pragma unroll
    for (int k = 0; k < 5; k++) { sl[k] = expf(sl[k] - mx); den += sl[k]; }
    float inv = 1.f / den;
#pragma unroll
    for (int k = 0; k < 5; k++) out[b * 5 + k] = sl[k] * inv;

    float vl[2];
#pragma unroll
    for (int k = 0; k < 2; k++) {
        float a = vb[k];
        for (int j = 0; j < 32; j++) a = fmaf(h[j], vw[k * 32 + j], a);
        vl[k] = a;
    }
    float m2 = fmaxf(vl[0], vl[1]);
    float e0 = expf(vl[0] - m2), e1 = expf(vl[1] - m2);
    float id = 1.f / (e0 + e1);
    out[320 + b * 2 + 0] = e0 * id;
    out[320 + b * 2 + 1] = e1 * id;
}

extern "C" void kernel_launch(void* const* d_in, const int* in_sizes, int n_in,
                              void* d_out, int out_size) {
    const float* x       = (const float*)d_in[0];
    const float* conv0_w = (const float*)d_in[1];
    const float* conv0_b = (const float*)d_in[2];
    const float* conv1_w = (const float*)d_in[3];
    const float* conv1_b = (const float*)d_in[4];
    const float* conv2_w = (const float*)d_in[5];
    const float* conv2_b = (const float*)d_in[6];
    const float* gn0_w   = (const float*)d_in[7];
    const float* gn0_b   = (const float*)d_in[8];
    const float* n1_w    = (const float*)d_in[9];
    const float* n1_b    = (const float*)d_in[10];
    const float* n2_w    = (const float*)d_in[11];
    const float* n2_b    = (const float*)d_in[12];
    const float* bn_g    = (const float*)d_in[13];
    const float* bn_b    = (const float*)d_in[14];
    const float* fc1_w   = (const float*)d_in[15];
    const float* fc1_b   = (const float*)d_in[16];
    const float* shape_w = (const float*)d_in[17];
    const float* shape_b = (const float*)d_in[18];
    const float* vern_w  = (const float*)d_in[19];
    const float* vern_b  = (const float*)d_in[20];
    float* out = (float*)d_out;

    const int smem0 = (23940 + 1176) * 4;
    const int smem1 = (25088 + 1600) * 4;
    const int smem2 = (6400 + 2304) * 4;
    const int smemg = (64 * 129 + 4096) * 4;
    cudaFuncSetAttribute(k_conv0, cudaFuncAttributeMaxDynamicSharedMemorySize, smem0);
    cudaFuncSetAttribute(k_conv1, cudaFuncAttributeMaxDynamicSharedMemorySize, smem1);
    cudaFuncSetAttribute(k_gemm,  cudaFuncAttributeMaxDynamicSharedMemorySize, smemg);

    k_conv0<<<64 * 7, 224, smem0>>>(x, conv0_w, conv0_b);
    k_stats0<<<64 * 8, 256>>>(gn0_w, gn0_b);
    k_conv1<<<128, 352, smem1>>>(conv1_w, conv1_b);
    k_entstats<<<64 * 16, 224>>>(0, 16, n1_w, n1_b);
    k_conv2<<<128, 352, smem2>>>(conv2_w, conv2_b);
    k_entstats<<<64 * 32, 224>>>(1, 32, n2_w, n2_b);
    k_bnstats<<<(F + 255) / 256, 256>>>(bn_g, bn_b);
    k_gemm<<<81, 256, smemg>>>(fc1_w);
    k_fcreduce<<<(B * 32 + 255) / 256, 256>>>(fc1_b);
    k_heads<<<1, 64>>>(shape_w, shape_b, vern_w, vern_b, out);
}

// round 3
// speedup vs baseline: 1.1839x; 1.1839x over previous
#include <cuda_runtime.h>
#include <math.h>

#define B 64
#define C0 8
#define HW0 3136
#define C1 16
#define HW1 324
#define C2 32
#define F 10368
#define EPSN 1e-5f

// ---------------- persistent scratch ----------------
__device__ float g_h0[B*C0*HW0];
__device__ float g_a0[B*C0], g_b0[B*C0];
__device__ float g_h1[B*C1*HW1];
__device__ float g_a1[B*C1], g_b1[B*C1];
__device__ float g_h2[B*C2*HW1];
__device__ float g_a2[B*C2], g_b2[B*C2];
__device__ float g_bnsc[F], g_bnsh[F];
__device__ float g_part[81*B*32];
__device__ float g_lut[26];

// ---------------- K1: conv0 7x7 s4 p2 (phase-swizzled smem, float4 weights) ----------------
// grid 448 = 64b x 7 tiles (8 output rows), block 224.
__global__ void k_conv0(const float* __restrict__ x, const float* __restrict__ w,
                        const float* __restrict__ bias) {
    extern __shared__ float sm[];
    float* s_in = sm;            // 3*35*4*57 = 23940
    float* s_w  = sm + 23940;    // [tap(147)][oc(8)] = 1176, 16B aligned
    int blk = blockIdx.x;
    int b = blk / 7, tile = blk - b * 7;
    int tid = threadIdx.x;

    for (int i = tid; i < 1176; i += 224) {
        int o = i / 147, rem = i - o * 147;
        s_w[rem * 8 + o] = w[i];
    }

    const float* xb = x + (size_t)b * 3 * 224 * 224;
    for (int i = tid; i < 23835; i += 224) {
        int ic = i / 7945;
        int rem = i - ic * 7945;
        int r = rem / 227, sc = rem - r * 227;
        int gr = tile * 32 - 2 + r, gc = sc - 2;
        float v = 0.f;
        if (gr >= 0 && gr < 224 && gc >= 0 && gc < 224)
            v = xb[(ic * 224 + gr) * 224 + gc];
        s_in[((ic * 35 + r) * 4 + (sc & 3)) * 57 + (sc >> 2)] = v;
    }
    __syncthreads();

    int r0 = tid / 56, ocol = tid - r0 * 56;
    float acc0[8], acc1[8];
#pragma unroll
    for (int o = 0; o < 8; o++) { acc0[o] = 0.f; acc1[o] = 0.f; }

    for (int ic = 0; ic < 3; ic++)
#pragma unroll
        for (int ky = 0; ky < 7; ky++) {
            int rowbase = (ic * 35 + r0 * 4 + ky) * 4;
            int tap0 = (ic * 49 + ky * 7) * 8;
#pragma unroll
            for (int kx = 0; kx < 7; kx++) {
                int idx = (rowbase + (kx & 3)) * 57 + ocol + (kx >> 2);
                float v0 = s_in[idx];
                float v1 = s_in[idx + 16 * 4 * 57];
                const float4* wq = (const float4*)(s_w + tap0 + kx * 8);
                float4 wa = wq[0], wb = wq[1];
                acc0[0] = fmaf(v0, wa.x, acc0[0]); acc1[0] = fmaf(v1, wa.x, acc1[0]);
                acc0[1] = fmaf(v0, wa.y, acc0[1]); acc1[1] = fmaf(v1, wa.y, acc1[1]);
                acc0[2] = fmaf(v0, wa.z, acc0[2]); acc1[2] = fmaf(v1, wa.z, acc1[2]);
                acc0[3] = fmaf(v0, wa.w, acc0[3]); acc1[3] = fmaf(v1, wa.w, acc1[3]);
                acc0[4] = fmaf(v0, wb.x, acc0[4]); acc1[4] = fmaf(v1, wb.x, acc1[4]);
                acc0[5] = fmaf(v0, wb.y, acc0[5]); acc1[5] = fmaf(v1, wb.y, acc1[5]);
                acc0[6] = fmaf(v0, wb.z, acc0[6]); acc1[6] = fmaf(v1, wb.z, acc1[6]);
                acc0[7] = fmaf(v0, wb.w, acc0[7]); acc1[7] = fmaf(v1, wb.w, acc1[7]);
            }
        }
    int orow0 = tile * 8 + r0;
#pragma unroll
    for (int o = 0; o < 8; o++) {
        float bv = bias[o];
        g_h0[((b * 8 + o) * 56 + orow0) * 56 + ocol]     = acc0[o] + bv;
        g_h0[((b * 8 + o) * 56 + orow0 + 4) * 56 + ocol] = acc1[o] + bv;
    }
}

// ---------------- K2: GroupNorm stats -> folded affine (+ entropy LUT init) ----------------
__global__ void k_stats0(const float* __restrict__ gw, const float* __restrict__ gb) {
    __shared__ float sred[32];
    int bc = blockIdx.x, c = bc & 7;
    if (bc == 0 && threadIdx.x < 26) {
        float pk = __fdiv_rn((float)threadIdx.x, 25.0f);
        float pc = fminf(fmaxf(pk, 1e-5f), 1.0f - 1e-5f);
        g_lut[threadIdx.x] = -pk * logf(pc);
    }
    const float* p = g_h0 + (size_t)bc * HW0;
    float s = 0.f, q = 0.f;
    for (int i = threadIdx.x; i < HW0; i += blockDim.x) {
        float v = p[i]; s += v; q = fmaf(v, v, q);
    }
    int lane = threadIdx.x & 31, wid = threadIdx.x >> 5;
#pragma unroll
    for (int o = 16; o > 0; o >>= 1) {
        s += __shfl_down_sync(0xffffffffu, s, o);
        q += __shfl_down_sync(0xffffffffu, q, o);
    }
    if (lane == 0) { sred[wid] = s; sred[wid + 8] = q; }
    __syncthreads();
    if (threadIdx.x == 0) {
        float S = 0.f, Q = 0.f;
        for (int wI = 0; wI < 8; wI++) { S += sred[wI]; Q += sred[wI + 8]; }
        float mu = S * (1.f / 3136.f);
        float var = Q * (1.f / 3136.f) - mu * mu;
        float a = rsqrtf(var + EPSN) * gw[c];
        g_a0[bc] = a;
        g_b0[bc] = gb[c] - mu * a;
    }
}

// ---------------- K3: conv1 5x5 s3 p1 on relu(a*h0+b), float4 weights ----------------
__global__ void k_conv1(const float* __restrict__ w, const float* __restrict__ bias) {
    extern __shared__ float sm[];
    float* s_in = sm;            // 25088
    float* s_w  = sm + 25088;    // [tap(200)][oc(8)] = 1600
    __shared__ float s_a[8], s_b[8];
    int b = blockIdx.x >> 1, ocb = (blockIdx.x & 1) * 8;
    int tid = threadIdx.x;

    if (tid < 8) { s_a[tid] = g_a0[b * 8 + tid]; s_b[tid] = g_b0[b * 8 + tid]; }
    for (int i = tid; i < 1600; i += blockDim.x) {
        int o = i / 200, rem = i - o * 200;
        s_w[rem * 8 + o] = w[(ocb + o) * 200 + rem];
    }
    __syncthreads();

    const float* h0b = g_h0 + (size_t)b * 8 * HW0;
    for (int i = tid; i < 25088; i += blockDim.x) {
        int ic = i / 3136;
        int rem = i - ic * 3136;
        int rr = rem / 56, cc = rem - rr * 56;
        int gr = rr - 1, gc = cc - 1;
        float v = 0.f;
        if (gr >= 0 && gc >= 0)
            v = fmaxf(fmaf(h0b[ic * 3136 + gr * 56 + gc], s_a[ic], s_b[ic]), 0.f);
        s_in[i] = v;
    }
    __syncthreads();

    if (tid < 324) {
        int oy = tid / 18, ox = tid - oy * 18;
        float acc[8];
#pragma unroll
        for (int o = 0; o < 8; o++) acc[o] = 0.f;
        for (int ic = 0; ic < 8; ic++)
#pragma unroll
            for (int ky = 0; ky < 5; ky++) {
                const float* ip = s_in + (ic * 56 + oy * 3 + ky) * 56 + ox * 3;
                int tap0 = (ic * 25 + ky * 5) * 8;
#pragma unroll
                for (int kx = 0; kx < 5; kx++) {
                    float v = ip[kx];
                    const float4* wq = (const float4*)(s_w + tap0 + kx * 8);
                    float4 wa = wq[0], wb = wq[1];
                    acc[0] = fmaf(v, wa.x, acc[0]);
                    acc[1] = fmaf(v, wa.y, acc[1]);
                    acc[2] = fmaf(v, wa.z, acc[2]);
                    acc[3] = fmaf(v, wa.w, acc[3]);
                    acc[4] = fmaf(v, wb.x, acc[4]);
                    acc[5] = fmaf(v, wb.y, acc[5]);
                    acc[6] = fmaf(v, wb.z, acc[6]);
                    acc[7] = fmaf(v, wb.w, acc[7]);
                }
            }
#pragma unroll
        for (int o = 0; o < 8; o++)
            g_h1[(b * 16 + ocb + o) * HW1 + tid] = acc[o] + bias[ocb + o];
    }
}

// ---------------- K4/K6: entropy + instance-norm stats per (b,c) ----------------
__global__ void __launch_bounds__(224) k_entstats(int which, int C,
                                                  const float* __restrict__ nw,
                                                  const float* __restrict__ nb) {
    __shared__ float s_ch[324];
    __shared__ float s_e[26];
    __shared__ float sred[24];
    const float* h = which ? g_h2 : g_h1;
    float* ga = which ? g_a2 : g_a1;
    float* gb = which ? g_b2 : g_b1;
    int bc = blockIdx.x, c = bc % C;
    int tid = threadIdx.x;

    float s = 0.f, q = 0.f;
    for (int i = tid; i < 324; i += 224) {
        float v = h[(size_t)bc * 324 + i];
        s_ch[i] = v; s += v; q = fmaf(v, v, q);
    }
    if (tid < 26) s_e[tid] = g_lut[tid];
    __syncthreads();

    float ep = 0.f;
    if (tid < 196) {
        int py = tid / 14, px = tid - py * 14;
        const float* pbase = s_ch + py * 18 + px;
        float mn = pbase[0], mx = pbase[0];
#pragma unroll
        for (int dy = 0; dy < 5; dy++)
#pragma unroll
            for (int dx = 0; dx < 5; dx++) {
                float v = pbase[dy * 18 + dx];
                mn = fminf(mn, v); mx = fmaxf(mx, v);
            }
        float rng = (mx > mn) ? (mx - mn) : 1.0f;
        float inv = __frcp_rn(rng);
        unsigned long long lo = 0ull, hi = 0ull;
        int c24 = 0;
#pragma unroll
        for (int dy = 0; dy < 5; dy++)
#pragma unroll
            for (int dx = 0; dx < 5; dx++) {
                float dv = pbase[dy * 18 + dx] - mn;
                float q0 = dv * inv;
                float r  = fmaf(-rng, q0, dv);
                float qq = fmaf(r, inv, q0);       // ~correctly rounded dv/rng
                float t  = qq * 25.0f;
                int bi = (int)t;                    // t >= 0 -> trunc == floor
                bi = bi > 24 ? 24 : bi;
                if (bi < 12)      lo += 1ull << (bi * 5);
                else if (bi < 24) hi += 1ull << ((bi - 12) * 5);
                else              c24++;
            }
#pragma unroll
        for (int k = 0; k < 12; k++) ep += s_e[(unsigned)(lo >> (k * 5)) & 31u];
#pragma unroll
        for (int k = 0; k < 12; k++) ep += s_e[(unsigned)(hi >> (k * 5)) & 31u];
        ep += s_e[c24];
    }

    int lane = tid & 31, wid = tid >> 5;   // 7 warps
#pragma unroll
    for (int o = 16; o > 0; o >>= 1) {
        s  += __shfl_down_sync(0xffffffffu, s, o);
        q  += __shfl_down_sync(0xffffffffu, q, o);
        ep += __shfl_down_sync(0xffffffffu, ep, o);
    }
    if (lane == 0) { sred[wid] = s; sred[wid + 8] = q; sred[wid + 16] = ep; }
    __syncthreads();
    if (tid == 0) {
        float S = 0.f, Q = 0.f, E = 0.f;
        for (int wI = 0; wI < 7; wI++) { S += sred[wI]; Q += sred[wI + 8]; E += sred[wI + 16]; }
        float ent = E * (1.0f / 196.0f);
        float mu = S * (1.0f / 324.0f);
        float var = (Q * (1.0f / 324.0f) - mu * mu) * (324.0f / 323.0f);
        float a = rsqrtf(var + EPSN) * nw[c] * ent;
        ga[bc] = a;
        gb[bc] = nb[c] - mu * a;
    }
}

// ---------------- K5: conv2 3x3 s1 p1 on relu(a*h1+b), float4 weights ----------------
__global__ void k_conv2(const float* __restrict__ w, const float* __restrict__ bias) {
    extern __shared__ float sm[];
    float* s_in = sm;            // 6400
    float* s_w  = sm + 6400;     // [tap(144)][oc(16)] = 2304
    __shared__ float s_a[16], s_b[16];
    int b = blockIdx.x >> 1, ocb = (blockIdx.x & 1) * 16;
    int tid = threadIdx.x;

    if (tid < 16) { s_a[tid] = g_a1[b * 16 + tid]; s_b[tid] = g_b1[b * 16 + tid]; }
    for (int i = tid; i < 2304; i += blockDim.x) {
        int o = i / 144, rem = i - o * 144;
        s_w[rem * 16 + o] = w[(ocb + o) * 144 + rem];
    }
    __syncthreads();

    for (int i = tid; i < 6400; i += blockDim.x) {
        int ic = i / 400;
        int rem = i - ic * 400;
        int rr = rem / 20, cc = rem - rr * 20;
        int gr = rr - 1, gc = cc - 1;
        float v = 0.f;
        if (gr >= 0 && gr < 18 && gc >= 0 && gc < 18)
            v = fmaxf(fmaf(g_h1[(b * 16 + ic) * 324 + gr * 18 + gc], s_a[ic], s_b[ic]), 0.f);
        s_in[i] = v;
    }
    __syncthreads();

    if (tid < 324) {
        int oy = tid / 18, ox = tid - oy * 18;
        float acc[16];
#pragma unroll
        for (int o = 0; o < 16; o++) acc[o] = 0.f;
        for (int ic = 0; ic < 16; ic++)
#pragma unroll
            for (int ky = 0; ky < 3; ky++) {
                const float* ip = s_in + (ic * 20 + oy + ky) * 20 + ox;
                int tap0 = (ic * 9 + ky * 3) * 16;
#pragma unroll
                for (int kx = 0; kx < 3; kx++) {
                    float v = ip[kx];
                    const float4* wq = (const float4*)(s_w + tap0 + kx * 16);
                    float4 w0 = wq[0], w1 = wq[1], w2 = wq[2], w3 = wq[3];
                    acc[0]  = fmaf(v, w0.x, acc[0]);
                    acc[1]  = fmaf(v, w0.y, acc[1]);
                    acc[2]  = fmaf(v, w0.z, acc[2]);
                    acc[3]  = fmaf(v, w0.w, acc[3]);
                    acc[4]  = fmaf(v, w1.x, acc[4]);
                    acc[5]  = fmaf(v, w1.y, acc[5]);
                    acc[6]  = fmaf(v, w1.z, acc[6]);
                    acc[7]  = fmaf(v, w1.w, acc[7]);
                    acc[8]  = fmaf(v, w2.x, acc[8]);
                    acc[9]  = fmaf(v, w2.y, acc[9]);
                    acc[10] = fmaf(v, w2.z, acc[10]);
                    acc[11] = fmaf(v, w2.w, acc[11]);
                    acc[12] = fmaf(v, w3.x, acc[12]);
                    acc[13] = fmaf(v, w3.y, acc[13]);
                    acc[14] = fmaf(v, w3.z, acc[14]);
                    acc[15] = fmaf(v, w3.w, acc[15]);
                }
            }
#pragma unroll
        for (int o = 0; o < 16; o++)
            g_h2[(b * 32 + ocb + o) * 324 + tid] = acc[o] + bias[ocb + o];
    }
}

// ---------------- K7: BatchNorm1d stats (batch axis, biased), 4-way b-split ----------------
// grid 162, block 256: 64 features/block, 4 threads per feature.
__global__ void k_bnstats(const float* __restrict__ bng, const float* __restrict__ bnb) {
    __shared__ float s_s[256], s_q[256];
    int tid = threadIdx.x;
    int fl = tid & 63, part = tid >> 6;
    int f = blockIdx.x * 64 + fl;
    int c = f / 324;
    float s = 0.f, q = 0.f;
#pragma unroll 4
    for (int b = part * 16; b < part * 16 + 16; b++) {
        float v = fmaxf(fmaf(g_h2[(size_t)b * F + f], g_a2[b * 32 + c], g_b2[b * 32 + c]), 0.f);
        s += v; q = fmaf(v, v, q);
    }
    s_s[tid] = s; s_q[tid] = q;
    __syncthreads();
    if (tid < 64) {
        float S = s_s[tid] + s_s[tid + 64] + s_s[tid + 128] + s_s[tid + 192];
        float Q = s_q[tid] + s_q[tid + 64] + s_q[tid + 128] + s_q[tid + 192];
        float mu = S * (1.f / 64.f);
        float var = Q * (1.f / 64.f) - mu * mu;
        float sc = bng[f] * rsqrtf(var + EPSN);
        g_bnsc[f] = sc;
        g_bnsh[f] = bnb[f] - mu * sc;
    }
}

// ---------------- K8: split-K GEMM, deterministic partials ----------------
__global__ void k_gemm(const float* __restrict__ fw) {
    extern __shared__ float sm[];
    float* s_h = sm;                 // 64 x 129
    float* s_w = sm + 64 * 129;      // 32 x 128
    int f0 = blockIdx.x * 128;
    int tid = threadIdx.x;

    for (int i = tid; i < 8192; i += 256) {
        int bb = i >> 7, k = i & 127;
        int f = f0 + k, c = f / 324;
        float v = fmaxf(fmaf(g_h2[(size_t)bb * F + f], g_a2[bb * 32 + c], g_b2[bb * 32 + c]), 0.f);
        s_h[bb * 129 + k] = fmaf(v, g_bnsc[f], g_bnsh[f]);
    }
    for (int i = tid; i < 4096; i += 256) {
        int j = i >> 7, k = i & 127;
        s_w[j * 128 + k] = fw[(size_t)j * F + f0 + k];
    }
    __syncthreads();

    int bb = tid & 63, jg = tid >> 6;
    float acc[8];
#pragma unroll
    for (int j = 0; j < 8; j++) acc[j] = 0.f;
    const float* hp = s_h + bb * 129;
    const float* wp = s_w + jg * 8 * 128;
    for (int k = 0; k < 128; k++) {
        float hv = hp[k];
#pragma unroll
        for (int j = 0; j < 8; j++) acc[j] = fmaf(hv, wp[j * 128 + k], acc[j]);
    }
#pragma unroll
    for (int j = 0; j < 8; j++)
        g_part[(size_t)blockIdx.x * 2048 + bb * 32 + jg * 8 + j] = acc[j];
}

// ---------------- K9: reduce partials + fc relu + heads + softmax ----------------
__global__ void k_heads(const float* __restrict__ fcb,
                        const float* __restrict__ sw, const float* __restrict__ sb,
                        const float* __restrict__ vw, const float* __restrict__ vb,
                        float* __restrict__ out) {
    __shared__ float s_y[2048];
    int tid = threadIdx.x;
    for (int t = tid; t < 2048; t += 1024) {
        float acc = 0.f;
#pragma unroll 8
        for (int p = 0; p < 81; p++) acc += g_part[(size_t)p * 2048 + t];
        s_y[t] = fmaxf(acc + fcb[t & 31], 0.f);
    }
    __syncthreads();
    if (tid < 64) {
        int b = tid;
        float h[32];
#pragma unroll
        for (int j = 0; j < 32; j++) h[j] = s_y[b * 32 + j];

        float sl[5];
#pragma unroll
        for (int k = 0; k < 5; k++) {
            float a = sb[k];
            for (int j = 0; j < 32; j++) a = fmaf(h[j], sw[k * 32 + j], a);
            sl[k] = a;
        }
        float mx = sl[0];
#pragma unroll
        for (int k = 1; k < 5; k++) mx = fmaxf(mx, sl[k]);
        float den = 0.f;
#pragma unroll
        for (int k = 0; k < 5; k++) { sl[k] = expf(sl[k] - mx); den += sl[k]; }
        float invd = 1.f / den;
#pragma unroll
        for (int k = 0; k < 5; k++) out[b * 5 + k] = sl[k] * invd;

        float vl[2];
#pragma unroll
        for (int k = 0; k < 2; k++) {
            float a = vb[k];
            for (int j = 0; j < 32; j++) a = fmaf(h[j], vw[k * 32 + j], a);
            vl[k] = a;
        }
        float m2 = fmaxf(vl[0], vl[1]);
        float e0 = expf(vl[0] - m2), e1 = expf(vl[1] - m2);
        float id = 1.f / (e0 + e1);
        out[320 + b * 2 + 0] = e0 * id;
        out[320 + b * 2 + 1] = e1 * id;
    }
}

extern "C" void kernel_launch(void* const* d_in, const int* in_sizes, int n_in,
                              void* d_out, int out_size) {
    const float* x       = (const float*)d_in[0];
    const float* conv0_w = (const float*)d_in[1];
    const float* conv0_b = (const float*)d_in[2];
    const float* conv1_w = (const float*)d_in[3];
    const float* conv1_b = (const float*)d_in[4];
    const float* conv2_w = (const float*)d_in[5];
    const float* conv2_b = (const float*)d_in[6];
    const float* gn0_w   = (const float*)d_in[7];
    const float* gn0_b   = (const float*)d_in[8];
    const float* n1_w    = (const float*)d_in[9];
    const float* n1_b    = (const float*)d_in[10];
    const float* n2_w    = (const float*)d_in[11];
    const float* n2_b    = (const float*)d_in[12];
    const float* bn_g    = (const float*)d_in[13];
    const float* bn_b    = (const float*)d_in[14];
    const float* fc1_w   = (const float*)d_in[15];
    const float* fc1_b   = (const float*)d_in[16];
    const float* shape_w = (const float*)d_in[17];
    const float* shape_b = (const float*)d_in[18];
    const float* vern_w  = (const float*)d_in[19];
    const float* vern_b  = (const float*)d_in[20];
    float* out = (float*)d_out;

    const int smem0 = (23940 + 1176) * 4;
    const int smem1 = (25088 + 1600) * 4;
    const int smem2 = (6400 + 2304) * 4;
    const int smemg = (64 * 129 + 4096) * 4;
    cudaFuncSetAttribute(k_conv0, cudaFuncAttributeMaxDynamicSharedMemorySize, smem0);
    cudaFuncSetAttribute(k_conv1, cudaFuncAttributeMaxDynamicSharedMemorySize, smem1);
    cudaFuncSetAttribute(k_gemm,  cudaFuncAttributeMaxDynamicSharedMemorySize, smemg);

    k_conv0<<<64 * 7, 224, smem0>>>(x, conv0_w, conv0_b);
    k_stats0<<<64 * 8, 256>>>(gn0_w, gn0_b);
    k_conv1<<<128, 352, smem1>>>(conv1_w, conv1_b);
    k_entstats<<<64 * 16, 224>>>(0, 16, n1_w, n1_b);
    k_conv2<<<128, 352, smem2>>>(conv2_w, conv2_b);
    k_entstats<<<64 * 32, 224>>>(1, 32, n2_w, n2_b);
    k_bnstats<<<162, 256>>>(bn_g, bn_b);
    k_gemm<<<81, 256, smemg>>>(fc1_w);
    k_heads<<<1, 1024>>>(fc1_b, shape_w, shape_b, vern_w, vern_b, out);
}

// round 4
// speedup vs baseline: 1.2709x; 1.0735x over previous
#include <cuda_runtime.h>
#include <math.h>

#define B 64
#define C0 8
#define HW0 3136
#define C1 16
#define HW1 324
#define C2 32
#define F 10368
#define EPSN 1e-5f

// ---------------- persistent scratch ----------------
__device__ float g_h0[B*C0*HW0];
__device__ float g_a0[B*C0], g_b0[B*C0];
__device__ float g_h1[B*C1*HW1];
__device__ float g_a1[B*C1], g_b1[B*C1];
__device__ float g_h2[B*C2*HW1];
__device__ float g_a2[B*C2], g_b2[B*C2];
__device__ float g_bnsc[F], g_bnsh[F];
__device__ float g_part[81*B*32];
__device__ float g_lut[26];

// ---------------- packed f32x2 helpers (sm_103a FFMA2 path) ----------------
__device__ __forceinline__ unsigned long long pk2(float lo, float hi) {
    unsigned long long r;
    asm("mov.b64 %0, {%1, %2};" : "=l"(r)
        : "r"(__float_as_uint(lo)), "r"(__float_as_uint(hi)));
    return r;
}
__device__ __forceinline__ void fma2(unsigned long long& d,
                                     unsigned long long a, unsigned long long b) {
    asm("fma.rn.f32x2 %0, %1, %2, %0;" : "+l"(d) : "l"(a), "l"(b));
}
__device__ __forceinline__ float2 upk(unsigned long long p) {
    unsigned int lo, hi;
    asm("mov.b64 {%0, %1}, %2;" : "=r"(lo), "=r"(hi) : "l"(p));
    return make_float2(__uint_as_float(lo), __uint_as_float(hi));
}

// ---------------- K1: conv0 7x7 s4 p2 (phase-swizzled smem, FFMA2) ----------------
// grid 448 = 64b x 7 tiles (8 output rows), block 224.
__global__ void k_conv0(const float* __restrict__ x, const float* __restrict__ w,
                        const float* __restrict__ bias) {
    extern __shared__ float sm[];
    float* s_in = sm;            // 3*35*4*57 = 23940 (= 5985 float4)
    float* s_w  = sm + 23940;    // [tap(147)][oc(8)] = 1176
    int blk = blockIdx.x;
    int b = blk / 7, tile = blk - b * 7;
    int tid = threadIdx.x;

    for (int i = tid; i < 1176; i += 224) {
        int o = i / 147, rem = i - o * 147;
        s_w[rem * 8 + o] = w[i];
    }
    // zero input tile (covers padding/halo), then vectorized fill
    for (int i = tid; i < 5985; i += 224)
        ((float4*)s_in)[i] = make_float4(0.f, 0.f, 0.f, 0.f);
    __syncthreads();

    const float* xb = x + (size_t)b * 3 * 224 * 224;
    // chunk c covers sc = 4c+2..4c+5 (gc = 4c..4c+3, 16B aligned); sc 0,1,226 stay 0
    for (int i = tid; i < 5880; i += 224) {
        int ic = i / 1960;
        int rem = i - ic * 1960;
        int r = rem / 56, cch = rem - r * 56;
        int gr = tile * 32 - 2 + r;
        if (gr >= 0 && gr < 224) {
            float4 v = *(const float4*)(xb + (ic * 224 + gr) * 224 + cch * 4);
            float* base = s_in + ((ic * 35 + r) * 4) * 57;
            base[2 * 57 + cch]     = v.x;   // sc=4c+2: phase 2, col c
            base[3 * 57 + cch]     = v.y;   // sc=4c+3: phase 3, col c
            base[0 * 57 + cch + 1] = v.z;   // sc=4c+4: phase 0, col c+1
            base[1 * 57 + cch + 1] = v.w;   // sc=4c+5: phase 1, col c+1
        }
    }
    __syncthreads();

    int r0 = tid / 56, ocol = tid - r0 * 56;
    unsigned long long a0[4], a1[4];
#pragma unroll
    for (int o = 0; o < 4; o++) { a0[o] = 0ull; a1[o] = 0ull; }

    for (int ic = 0; ic < 3; ic++)
#pragma unroll
        for (int ky = 0; ky < 7; ky++) {
            int rowbase = (ic * 35 + r0 * 4 + ky) * 4;
            int tap0 = (ic * 49 + ky * 7) * 8;
#pragma unroll
            for (int kx = 0; kx < 7; kx++) {
                int idx = (rowbase + (kx & 3)) * 57 + ocol + (kx >> 2);
                float v0 = s_in[idx];
                float v1 = s_in[idx + 16 * 4 * 57];
                unsigned long long v0p = pk2(v0, v0);
                unsigned long long v1p = pk2(v1, v1);
                const ulonglong2* wq = (const ulonglong2*)(s_w + tap0 + kx * 8);
                ulonglong2 wA = wq[0], wB = wq[1];
                fma2(a0[0], v0p, wA.x); fma2(a0[1], v0p, wA.y);
                fma2(a0[2], v0p, wB.x); fma2(a0[3], v0p, wB.y);
                fma2(a1[0], v1p, wA.x); fma2(a1[1], v1p, wA.y);
                fma2(a1[2], v1p, wB.x); fma2(a1[3], v1p, wB.y);
            }
        }
    int orow0 = tile * 8 + r0;
#pragma unroll
    for (int o2 = 0; o2 < 4; o2++) {
        float2 p0 = upk(a0[o2]);
        float2 p1 = upk(a1[o2]);
        int o = o2 * 2;
        float bv0 = bias[o], bv1 = bias[o + 1];
        g_h0[((b * 8 + o) * 56 + orow0) * 56 + ocol]         = p0.x + bv0;
        g_h0[((b * 8 + o + 1) * 56 + orow0) * 56 + ocol]     = p0.y + bv1;
        g_h0[((b * 8 + o) * 56 + orow0 + 4) * 56 + ocol]     = p1.x + bv0;
        g_h0[((b * 8 + o + 1) * 56 + orow0 + 4) * 56 + ocol] = p1.y + bv1;
    }
}

// ---------------- K2: GroupNorm stats -> folded affine (+ entropy LUT init) ----------------
__global__ void k_stats0(const float* __restrict__ gw, const float* __restrict__ gb) {
    __shared__ float sred[32];
    int bc = blockIdx.x, c = bc & 7;
    if (bc == 0 && threadIdx.x < 26) {
        float pk = __fdiv_rn((float)threadIdx.x, 25.0f);
        float pc = fminf(fmaxf(pk, 1e-5f), 1.0f - 1e-5f);
        g_lut[threadIdx.x] = -pk * logf(pc);
    }
    const float* p = g_h0 + (size_t)bc * HW0;
    float s = 0.f, q = 0.f;
    for (int i = threadIdx.x; i < HW0; i += blockDim.x) {
        float v = p[i]; s += v; q = fmaf(v, v, q);
    }
    int lane = threadIdx.x & 31, wid = threadIdx.x >> 5;
#pragma unroll
    for (int o = 16; o > 0; o >>= 1) {
        s += __shfl_down_sync(0xffffffffu, s, o);
        q += __shfl_down_sync(0xffffffffu, q, o);
    }
    if (lane == 0) { sred[wid] = s; sred[wid + 8] = q; }
    __syncthreads();
    if (threadIdx.x == 0) {
        float S = 0.f, Q = 0.f;
        for (int wI = 0; wI < 8; wI++) { S += sred[wI]; Q += sred[wI + 8]; }
        float mu = S * (1.f / 3136.f);
        float var = Q * (1.f / 3136.f) - mu * mu;
        float a = rsqrtf(var + EPSN) * gw[c];
        g_a0[bc] = a;
        g_b0[bc] = gb[c] - mu * a;
    }
}

// ---------------- K3: conv1 5x5 s3 p1 on relu(a*h0+b), FFMA2 ----------------
__global__ void k_conv1(const float* __restrict__ w, const float* __restrict__ bias) {
    extern __shared__ float sm[];
    float* s_in = sm;            // 25088
    float* s_w  = sm + 25088;    // [tap(200)][oc(8)] = 1600
    __shared__ float s_a[8], s_b[8];
    int b = blockIdx.x >> 1, ocb = (blockIdx.x & 1) * 8;
    int tid = threadIdx.x;

    if (tid < 8) { s_a[tid] = g_a0[b * 8 + tid]; s_b[tid] = g_b0[b * 8 + tid]; }
    for (int i = tid; i < 1600; i += blockDim.x) {
        int o = i / 200, rem = i - o * 200;
        s_w[rem * 8 + o] = w[(ocb + o) * 200 + rem];
    }
    __syncthreads();

    const float* h0b = g_h0 + (size_t)b * 8 * HW0;
    for (int i = tid; i < 25088; i += blockDim.x) {
        int ic = i / 3136;
        int rem = i - ic * 3136;
        int rr = rem / 56, cc = rem - rr * 56;
        int gr = rr - 1, gc = cc - 1;
        float v = 0.f;
        if (gr >= 0 && gc >= 0)
            v = fmaxf(fmaf(h0b[ic * 3136 + gr * 56 + gc], s_a[ic], s_b[ic]), 0.f);
        s_in[i] = v;
    }
    __syncthreads();

    if (tid < 324) {
        int oy = tid / 18, ox = tid - oy * 18;
        unsigned long long acc[4];
#pragma unroll
        for (int o = 0; o < 4; o++) acc[o] = 0ull;
        for (int ic = 0; ic < 8; ic++)
#pragma unroll
            for (int ky = 0; ky < 5; ky++) {
                const float* ip = s_in + (ic * 56 + oy * 3 + ky) * 56 + ox * 3;
                int tap0 = (ic * 25 + ky * 5) * 8;
#pragma unroll
                for (int kx = 0; kx < 5; kx++) {
                    unsigned long long vp = pk2(ip[kx], ip[kx]);
                    const ulonglong2* wq = (const ulonglong2*)(s_w + tap0 + kx * 8);
                    ulonglong2 wA = wq[0], wB = wq[1];
                    fma2(acc[0], vp, wA.x); fma2(acc[1], vp, wA.y);
                    fma2(acc[2], vp, wB.x); fma2(acc[3], vp, wB.y);
                }
            }
#pragma unroll
        for (int o2 = 0; o2 < 4; o2++) {
            float2 p = upk(acc[o2]);
            int o = o2 * 2;
            g_h1[(b * 16 + ocb + o) * HW1 + tid]     = p.x + bias[ocb + o];
            g_h1[(b * 16 + ocb + o + 1) * HW1 + tid] = p.y + bias[ocb + o + 1];
        }
    }
}

// ---------------- K4/K6: entropy + instance-norm stats per (b,c) ----------------
__global__ void __launch_bounds__(224) k_entstats(int which, int C,
                                                  const float* __restrict__ nw,
                                                  const float* __restrict__ nb) {
    __shared__ float s_ch[324];
    __shared__ float s_e[26];
    __shared__ float sred[24];
    const float* h = which ? g_h2 : g_h1;
    float* ga = which ? g_a2 : g_a1;
    float* gb = which ? g_b2 : g_b1;
    int bc = blockIdx.x, c = bc % C;
    int tid = threadIdx.x;

    float s = 0.f, q = 0.f;
    for (int i = tid; i < 324; i += 224) {
        float v = h[(size_t)bc * 324 + i];
        s_ch[i] = v; s += v; q = fmaf(v, v, q);
    }
    if (tid < 26) s_e[tid] = g_lut[tid];
    __syncthreads();

    float ep = 0.f;
    if (tid < 196) {
        int py = tid / 14, px = tid - py * 14;
        const float* pbase = s_ch + py * 18 + px;
        float mn = pbase[0], mx = pbase[0];
#pragma unroll
        for (int dy = 0; dy < 5; dy++)
#pragma unroll
            for (int dx = 0; dx < 5; dx++) {
                float v = pbase[dy * 18 + dx];
                mn = fminf(mn, v); mx = fmaxf(mx, v);
            }
        float rng = (mx > mn) ? (mx - mn) : 1.0f;
        float s25 = __frcp_rn(rng) * 25.0f;
        float ms  = -mn * s25;
        unsigned long long lo = 0ull, hi = 0ull;
        int c24 = 0;
#pragma unroll
        for (int dy = 0; dy < 5; dy++)
#pragma unroll
            for (int dx = 0; dx < 5; dx++) {
                float t = fmaf(pbase[dy * 18 + dx], s25, ms);
                int bi = (int)t;                 // t >= -ulp -> trunc ok
                bi = bi > 24 ? 24 : bi;
                if (bi < 12)      lo += 1ull << (bi * 5);
                else if (bi < 24) hi += 1ull << ((bi - 12) * 5);
                else              c24++;
            }
#pragma unroll
        for (int k = 0; k < 12; k++) ep += s_e[(unsigned)(lo >> (k * 5)) & 31u];
#pragma unroll
        for (int k = 0; k < 12; k++) ep += s_e[(unsigned)(hi >> (k * 5)) & 31u];
        ep += s_e[c24];
    }

    int lane = tid & 31, wid = tid >> 5;   // 7 warps
#pragma unroll
    for (int o = 16; o > 0; o >>= 1) {
        s  += __shfl_down_sync(0xffffffffu, s, o);
        q  += __shfl_down_sync(0xffffffffu, q, o);
        ep += __shfl_down_sync(0xffffffffu, ep, o);
    }
    if (lane == 0) { sred[wid] = s; sred[wid + 8] = q; sred[wid + 16] = ep; }
    __syncthreads();
    if (tid == 0) {
        float S = 0.f, Q = 0.f, E = 0.f;
        for (int wI = 0; wI < 7; wI++) { S += sred[wI]; Q += sred[wI + 8]; E += sred[wI + 16]; }
        float ent = E * (1.0f / 196.0f);
        float mu = S * (1.0f / 324.0f);
        float var = (Q * (1.0f / 324.0f) - mu * mu) * (324.0f / 323.0f);
        float a = rsqrtf(var + EPSN) * nw[c] * ent;
        ga[bc] = a;
        gb[bc] = nb[c] - mu * a;
    }
}

// ---------------- K5: conv2 3x3 s1 p1 on relu(a*h1+b), FFMA2 ----------------
__global__ void k_conv2(const float* __restrict__ w, const float* __restrict__ bias) {
    extern __shared__ float sm[];
    float* s_in = sm;            // 6400
    float* s_w  = sm + 6400;     // [tap(144)][oc(16)] = 2304
    __shared__ float s_a[16], s_b[16];
    int b = blockIdx.x >> 1, ocb = (blockIdx.x & 1) * 16;
    int tid = threadIdx.x;

    if (tid < 16) { s_a[tid] = g_a1[b * 16 + tid]; s_b[tid] = g_b1[b * 16 + tid]; }
    for (int i = tid; i < 2304; i += blockDim.x) {
        int o = i / 144, rem = i - o * 144;
        s_w[rem * 16 + o] = w[(ocb + o) * 144 + rem];
    }
    __syncthreads();

    for (int i = tid; i < 6400; i += blockDim.x) {
        int ic = i / 400;
        int rem = i - ic * 400;
        int rr = rem / 20, cc = rem - rr * 20;
        int gr = rr - 1, gc = cc - 1;
        float v = 0.f;
        if (gr >= 0 && gr < 18 && gc >= 0 && gc < 18)
            v = fmaxf(fmaf(g_h1[(b * 16 + ic) * 324 + gr * 18 + gc], s_a[ic], s_b[ic]), 0.f);
        s_in[i] = v;
    }
    __syncthreads();

    if (tid < 324) {
        int oy = tid / 18, ox = tid - oy * 18;
        unsigned long long acc[8];
#pragma unroll
        for (int o = 0; o < 8; o++) acc[o] = 0ull;
        for (int ic = 0; ic < 16; ic++)
#pragma unroll
            for (int ky = 0; ky < 3; ky++) {
                const float* ip = s_in + (ic * 20 + oy + ky) * 20 + ox;
                int tap0 = (ic * 9 + ky * 3) * 16;
#pragma unroll
                for (int kx = 0; kx < 3; kx++) {
                    unsigned long long vp = pk2(ip[kx], ip[kx]);
                    const ulonglong2* wq = (const ulonglong2*)(s_w + tap0 + kx * 16);
                    ulonglong2 w0 = wq[0], w1 = wq[1], w2 = wq[2], w3 = wq[3];
                    fma2(acc[0], vp, w0.x); fma2(acc[1], vp, w0.y);
                    fma2(acc[2], vp, w1.x); fma2(acc[3], vp, w1.y);
                    fma2(acc[4], vp, w2.x); fma2(acc[5], vp, w2.y);
                    fma2(acc[6], vp, w3.x); fma2(acc[7], vp, w3.y);
                }
            }
#pragma unroll
        for (int o2 = 0; o2 < 8; o2++) {
            float2 p = upk(acc[o2]);
            int o = o2 * 2;
            g_h2[(b * 32 + ocb + o) * 324 + tid]     = p.x + bias[ocb + o];
            g_h2[(b * 32 + ocb + o + 1) * 324 + tid] = p.y + bias[ocb + o + 1];
        }
    }
}

// ---------------- K7: BatchNorm1d stats (batch axis, biased), 4-way b-split ----------------
__global__ void k_bnstats(const float* __restrict__ bng, const float* __restrict__ bnb) {
    __shared__ float s_s[256], s_q[256];
    int tid = threadIdx.x;
    int fl = tid & 63, part = tid >> 6;
    int f = blockIdx.x * 64 + fl;
    int c = f / 324;
    float s = 0.f, q = 0.f;
#pragma unroll 4
    for (int b = part * 16; b < part * 16 + 16; b++) {
        float v = fmaxf(fmaf(g_h2[(size_t)b * F + f], g_a2[b * 32 + c], g_b2[b * 32 + c]), 0.f);
        s += v; q = fmaf(v, v, q);
    }
    s_s[tid] = s; s_q[tid] = q;
    __syncthreads();
    if (tid < 64) {
        float S = s_s[tid] + s_s[tid + 64] + s_s[tid + 128] + s_s[tid + 192];
        float Q = s_q[tid] + s_q[tid + 64] + s_q[tid + 128] + s_q[tid + 192];
        float mu = S * (1.f / 64.f);
        float var = Q * (1.f / 64.f) - mu * mu;
        float sc = bng[f] * rsqrtf(var + EPSN);
        g_bnsc[f] = sc;
        g_bnsh[f] = bnb[f] - mu * sc;
    }
}

// ---------------- K8: split-K GEMM, deterministic partials, FFMA2 over k-pairs ----------------
__global__ void k_gemm(const float* __restrict__ fw) {
    extern __shared__ float sm[];
    float* s_h = sm;                 // 64 x 132 (pad 132: float4-aligned)
    float* s_w = sm + 64 * 132;      // 32 x 128
    int f0 = blockIdx.x * 128;
    int tid = threadIdx.x;

    for (int i = tid; i < 8192; i += 256) {
        int bb = i >> 7, k = i & 127;
        int f = f0 + k, c = f / 324;
        float v = fmaxf(fmaf(g_h2[(size_t)bb * F + f], g_a2[bb * 32 + c], g_b2[bb * 32 + c]), 0.f);
        s_h[bb * 132 + k] = fmaf(v, g_bnsc[f], g_bnsh[f]);
    }
    for (int i = tid; i < 4096; i += 256) {
        int j = i >> 7, k = i & 127;
        s_w[j * 128 + k] = fw[(size_t)j * F + f0 + k];
    }
    __syncthreads();

    int bb = tid & 63, jg = tid >> 6;
    unsigned long long acc2[8];
#pragma unroll
    for (int j = 0; j < 8; j++) acc2[j] = 0ull;
    const float* hp = s_h + bb * 132;
    const float* wp = s_w + jg * 8 * 128;
    for (int k = 0; k < 128; k += 4) {
        ulonglong2 h2 = *(const ulonglong2*)(hp + k);
#pragma unroll
        for (int j = 0; j < 8; j++) {
            ulonglong2 w2 = *(const ulonglong2*)(wp + j * 128 + k);
            fma2(acc2[j], h2.x, w2.x);
            fma2(acc2[j], h2.y, w2.y);
        }
    }
#pragma unroll
    for (int j = 0; j < 8; j++) {
        float2 p = upk(acc2[j]);
        g_part[(size_t)blockIdx.x * 2048 + bb * 32 + jg * 8 + j] = p.x + p.y;
    }
}

// ---------------- K9: reduce partials + fc relu + heads + softmax ----------------
__global__ void k_heads(const float* __restrict__ fcb,
                        const float* __restrict__ sw, const float* __restrict__ sb,
                        const float* __restrict__ vw, const float* __restrict__ vb,
                        float* __restrict__ out) {
    __shared__ float s_y[2048];
    int tid = threadIdx.x;
    for (int t = tid; t < 2048; t += 1024) {
        float acc = 0.f;
#pragma unroll 8
        for (int p = 0; p < 81; p++) acc += g_part[(size_t)p * 2048 + t];
        s_y[t] = fmaxf(acc + fcb[t & 31], 0.f);
    }
    __syncthreads();
    if (tid < 64) {
        int b = tid;
        float h[32];
#pragma unroll
        for (int j = 0; j < 32; j++) h[j] = s_y[b * 32 + j];

        float sl[5];
#pragma unroll
        for (int k = 0; k < 5; k++) {
            float a = sb[k];
            for (int j = 0; j < 32; j++) a = fmaf(h[j], sw[k * 32 + j], a);
            sl[k] = a;
        }
        float mx = sl[0];
#pragma unroll
        for (int k = 1; k < 5; k++) mx = fmaxf(mx, sl[k]);
        float den = 0.f;
#pragma unroll
        for (int k = 0; k < 5; k++) { sl[k] = expf(sl[k] - mx); den += sl[k]; }
        float invd = 1.f / den;
#pragma unroll
        for (int k = 0; k < 5; k++) out[b * 5 + k] = sl[k] * invd;

        float vl[2];
#pragma unroll
        for (int k = 0; k < 2; k++) {
            float a = vb[k];
            for (int j = 0; j < 32; j++) a = fmaf(h[j], vw[k * 32 + j], a);
            vl[k] = a;
        }
        float m2 = fmaxf(vl[0], vl[1]);
        float e0 = expf(vl[0] - m2), e1 = expf(vl[1] - m2);
        float id = 1.f / (e0 + e1);
        out[320 + b * 2 + 0] = e0 * id;
        out[320 + b * 2 + 1] = e1 * id;
    }
}

extern "C" void kernel_launch(void* const* d_in, const int* in_sizes, int n_in,
                              void* d_out, int out_size) {
    const float* x       = (const float*)d_in[0];
    const float* conv0_w = (const float*)d_in[1];
    const float* conv0_b = (const float*)d_in[2];
    const float* conv1_w = (const float*)d_in[3];
    const float* conv1_b = (const float*)d_in[4];
    const float* conv2_w = (const float*)d_in[5];
    const float* conv2_b = (const float*)d_in[6];
    const float* gn0_w   = (const float*)d_in[7];
    const float* gn0_b   = (const float*)d_in[8];
    const float* n1_w    = (const float*)d_in[9];
    const float* n1_b    = (const float*)d_in[10];
    const float* n2_w    = (const float*)d_in[11];
    const float* n2_b    = (const float*)d_in[12];
    const float* bn_g    = (const float*)d_in[13];
    const float* bn_b    = (const float*)d_in[14];
    const float* fc1_w   = (const float*)d_in[15];
    const float* fc1_b   = (const float*)d_in[16];
    const float* shape_w = (const float*)d_in[17];
    const float* shape_b = (const float*)d_in[18];
    const float* vern_w  = (const float*)d_in[19];
    const float* vern_b  = (const float*)d_in[20];
    float* out = (float*)d_out;

    const int smem0 = (23940 + 1176) * 4;
    const int smem1 = (25088 + 1600) * 4;
    const int smem2 = (6400 + 2304) * 4;
    const int smemg = (64 * 132 + 4096) * 4;
    cudaFuncSetAttribute(k_conv0, cudaFuncAttributeMaxDynamicSharedMemorySize, smem0);
    cudaFuncSetAttribute(k_conv1, cudaFuncAttributeMaxDynamicSharedMemorySize, smem1);
    cudaFuncSetAttribute(k_gemm,  cudaFuncAttributeMaxDynamicSharedMemorySize, smemg);

    k_conv0<<<64 * 7, 224, smem0>>>(x, conv0_w, conv0_b);
    k_stats0<<<64 * 8, 256>>>(gn0_w, gn0_b);
    k_conv1<<<128, 352, smem1>>>(conv1_w, conv1_b);
    k_entstats<<<64 * 16, 224>>>(0, 16, n1_w, n1_b);
    k_conv2<<<128, 352, smem2>>>(conv2_w, conv2_b);
    k_entstats<<<64 * 32, 224>>>(1, 32, n2_w, n2_b);
    k_bnstats<<<162, 256>>>(bn_g, bn_b);
    k_gemm<<<81, 256, smemg>>>(fc1_w);
    k_heads<<<1, 1024>>>(fc1_b, shape_w, shape_b, vern_w, vern_b, out);
}

// round 5
// speedup vs baseline: 1.2891x; 1.0144x over previous
#include <cuda_runtime.h>
#include <math.h>

#define B 64
#define C0 8
#define HW0 3136
#define C1 16
#define HW1 324
#define C2 32
#define F 10368
#define EPSN 1e-5f

// ---------------- persistent scratch ----------------
__device__ float g_h0[B*C0*HW0];
__device__ float g_a0[B*C0], g_b0[B*C0];
__device__ float g_h1[B*C1*HW1];
__device__ float g_a1[B*C1], g_b1[B*C1];
__device__ float g_h2[B*C2*HW1];
__device__ float g_a2[B*C2], g_b2[B*C2];
__device__ float g_part[81*B*32];
__device__ float g_lut[26];

// ---------------- packed f32x2 helpers (sm_103a FFMA2 path) ----------------
__device__ __forceinline__ unsigned long long pk2(float lo, float hi) {
    unsigned long long r;
    asm("mov.b64 %0, {%1, %2};" : "=l"(r)
        : "r"(__float_as_uint(lo)), "r"(__float_as_uint(hi)));
    return r;
}
__device__ __forceinline__ void fma2(unsigned long long& d,
                                     unsigned long long a, unsigned long long b) {
    asm("fma.rn.f32x2 %0, %1, %2, %0;" : "+l"(d) : "l"(a), "l"(b));
}
__device__ __forceinline__ float2 upk(unsigned long long p) {
    unsigned int lo, hi;
    asm("mov.b64 {%0, %1}, %2;" : "=r"(lo), "=r"(hi) : "l"(p));
    return make_float2(__uint_as_float(lo), __uint_as_float(hi));
}

// ---------------- per-patch entropy (25 values, 18-stride rows) ----------------
__device__ __forceinline__ float patch_entropy(const float* __restrict__ pbase,
                                               const float* __restrict__ s_e) {
    float v[25];
#pragma unroll
    for (int dy = 0; dy < 5; dy++)
#pragma unroll
        for (int dx = 0; dx < 5; dx++)
            v[dy * 5 + dx] = pbase[dy * 18 + dx];
    float mn = v[0], mx = v[0];
#pragma unroll
    for (int i = 1; i < 25; i++) { mn = fminf(mn, v[i]); mx = fmaxf(mx, v[i]); }
    float rng = (mx > mn) ? (mx - mn) : 1.0f;
    float s25 = __frcp_rn(rng) * 25.0f;
    float ms  = -mn * s25;
    unsigned long long lo = 0ull, hi = 0ull;
    int c24 = 0;
#pragma unroll
    for (int i = 0; i < 25; i++) {
        float t = fmaf(v[i], s25, ms);
        int bi = (int)t;
        bi = bi > 24 ? 24 : bi;
        if (bi < 12)      lo += 1ull << (bi * 5);
        else if (bi < 24) hi += 1ull << ((bi - 12) * 5);
        else              c24++;
    }
    float ep = 0.f;
#pragma unroll
    for (int k = 0; k < 12; k++) ep += s_e[(unsigned)(lo >> (k * 5)) & 31u];
#pragma unroll
    for (int k = 0; k < 12; k++) ep += s_e[(unsigned)(hi >> (k * 5)) & 31u];
    return ep + s_e[c24];
}

// ---------------- K1: conv0 7x7 s4 p2 (phase-swizzled smem, FFMA2) ----------------
__global__ void k_conv0(const float* __restrict__ x, const float* __restrict__ w,
                        const float* __restrict__ bias) {
    extern __shared__ float sm[];
    float* s_in = sm;            // 23940
    float* s_w  = sm + 23940;    // 1176
    int blk = blockIdx.x;
    int b = blk / 7, tile = blk - b * 7;
    int tid = threadIdx.x;

    for (int i = tid; i < 1176; i += 224) {
        int o = i / 147, rem = i - o * 147;
        s_w[rem * 8 + o] = w[i];
    }
    for (int i = tid; i < 5985; i += 224)
        ((float4*)s_in)[i] = make_float4(0.f, 0.f, 0.f, 0.f);
    __syncthreads();

    const float* xb = x + (size_t)b * 3 * 224 * 224;
    for (int i = tid; i < 5880; i += 224) {
        int ic = i / 1960;
        int rem = i - ic * 1960;
        int r = rem / 56, cch = rem - r * 56;
        int gr = tile * 32 - 2 + r;
        if (gr >= 0 && gr < 224) {
            float4 v = *(const float4*)(xb + (ic * 224 + gr) * 224 + cch * 4);
            float* base = s_in + ((ic * 35 + r) * 4) * 57;
            base[2 * 57 + cch]     = v.x;
            base[3 * 57 + cch]     = v.y;
            base[0 * 57 + cch + 1] = v.z;
            base[1 * 57 + cch + 1] = v.w;
        }
    }
    __syncthreads();

    int r0 = tid / 56, ocol = tid - r0 * 56;
    unsigned long long a0[4], a1[4];
#pragma unroll
    for (int o = 0; o < 4; o++) { a0[o] = 0ull; a1[o] = 0ull; }

    for (int ic = 0; ic < 3; ic++)
#pragma unroll
        for (int ky = 0; ky < 7; ky++) {
            int rowbase = (ic * 35 + r0 * 4 + ky) * 4;
            int tap0 = (ic * 49 + ky * 7) * 8;
#pragma unroll
            for (int kx = 0; kx < 7; kx++) {
                int idx = (rowbase + (kx & 3)) * 57 + ocol + (kx >> 2);
                float v0 = s_in[idx];
                float v1 = s_in[idx + 16 * 4 * 57];
                unsigned long long v0p = pk2(v0, v0);
                unsigned long long v1p = pk2(v1, v1);
                const ulonglong2* wq = (const ulonglong2*)(s_w + tap0 + kx * 8);
                ulonglong2 wA = wq[0], wB = wq[1];
                fma2(a0[0], v0p, wA.x); fma2(a0[1], v0p, wA.y);
                fma2(a0[2], v0p, wB.x); fma2(a0[3], v0p, wB.y);
                fma2(a1[0], v1p, wA.x); fma2(a1[1], v1p, wA.y);
                fma2(a1[2], v1p, wB.x); fma2(a1[3], v1p, wB.y);
            }
        }
    int orow0 = tile * 8 + r0;
#pragma unroll
    for (int o2 = 0; o2 < 4; o2++) {
        float2 p0 = upk(a0[o2]);
        float2 p1 = upk(a1[o2]);
        int o = o2 * 2;
        float bv0 = bias[o], bv1 = bias[o + 1];
        g_h0[((b * 8 + o) * 56 + orow0) * 56 + ocol]         = p0.x + bv0;
        g_h0[((b * 8 + o + 1) * 56 + orow0) * 56 + ocol]     = p0.y + bv1;
        g_h0[((b * 8 + o) * 56 + orow0 + 4) * 56 + ocol]     = p1.x + bv0;
        g_h0[((b * 8 + o + 1) * 56 + orow0 + 4) * 56 + ocol] = p1.y + bv1;
    }
}

// ---------------- K2: GroupNorm stats -> folded affine (+ entropy LUT init) ----------------
__global__ void k_stats0(const float* __restrict__ gw, const float* __restrict__ gb) {
    __shared__ float sred[32];
    int bc = blockIdx.x, c = bc & 7;
    if (bc == 0 && threadIdx.x < 26) {
        float pk = __fdiv_rn((float)threadIdx.x, 25.0f);
        float pc = fminf(fmaxf(pk, 1e-5f), 1.0f - 1e-5f);
        g_lut[threadIdx.x] = -pk * logf(pc);
    }
    const float* p = g_h0 + (size_t)bc * HW0;
    float s = 0.f, q = 0.f;
    for (int i = threadIdx.x; i < HW0; i += blockDim.x) {
        float v = p[i]; s += v; q = fmaf(v, v, q);
    }
    int lane = threadIdx.x & 31, wid = threadIdx.x >> 5;
#pragma unroll
    for (int o = 16; o > 0; o >>= 1) {
        s += __shfl_down_sync(0xffffffffu, s, o);
        q += __shfl_down_sync(0xffffffffu, q, o);
    }
    if (lane == 0) { sred[wid] = s; sred[wid + 8] = q; }
    __syncthreads();
    if (threadIdx.x == 0) {
        float S = 0.f, Q = 0.f;
        for (int wI = 0; wI < 8; wI++) { S += sred[wI]; Q += sred[wI + 8]; }
        float mu = S * (1.f / 3136.f);
        float var = Q * (1.f / 3136.f) - mu * mu;
        float a = rsqrtf(var + EPSN) * gw[c];
        g_a0[bc] = a;
        g_b0[bc] = gb[c] - mu * a;
    }
}

// ---------------- K3: conv1 5x5 s3 p1 + fused entropy/instance-norm stats ----------------
// grid 128 = 64b x 2 halves (8 oc each), block 352.
// dyn smem: s_in 25088 | s_w 1600 | s_ch 2592 | s_ep 1568
__global__ void k_conv1ent(const float* __restrict__ w, const float* __restrict__ bias,
                           const float* __restrict__ nw, const float* __restrict__ nb) {
    extern __shared__ float sm[];
    float* s_in = sm;
    float* s_w  = sm + 25088;
    float* s_ch = sm + 25088 + 1600;
    float* s_ep = sm + 25088 + 1600 + 2592;
    __shared__ float s_a[8], s_b[8];
    __shared__ float s_e[26];
    int b = blockIdx.x >> 1, ocb = (blockIdx.x & 1) * 8;
    int tid = threadIdx.x;

    if (tid < 8) { s_a[tid] = g_a0[b * 8 + tid]; s_b[tid] = g_b0[b * 8 + tid]; }
    if (tid >= 32 && tid < 58) s_e[tid - 32] = g_lut[tid - 32];
    for (int i = tid; i < 1600; i += 352) {
        int o = i / 200, rem = i - o * 200;
        s_w[rem * 8 + o] = w[(ocb + o) * 200 + rem];
    }
    __syncthreads();

    const float* h0b = g_h0 + (size_t)b * 8 * HW0;
    for (int i = tid; i < 25088; i += 352) {
        int ic = i / 3136;
        int rem = i - ic * 3136;
        int rr = rem / 56, cc = rem - rr * 56;
        int gr = rr - 1, gc = cc - 1;
        float v = 0.f;
        if (gr >= 0 && gc >= 0)
            v = fmaxf(fmaf(h0b[ic * 3136 + gr * 56 + gc], s_a[ic], s_b[ic]), 0.f);
        s_in[i] = v;
    }
    __syncthreads();

    if (tid < 324) {
        int oy = tid / 18, ox = tid - oy * 18;
        unsigned long long acc[4];
#pragma unroll
        for (int o = 0; o < 4; o++) acc[o] = 0ull;
        for (int ic = 0; ic < 8; ic++)
#pragma unroll
            for (int ky = 0; ky < 5; ky++) {
                const float* ip = s_in + (ic * 56 + oy * 3 + ky) * 56 + ox * 3;
                int tap0 = (ic * 25 + ky * 5) * 8;
#pragma unroll
                for (int kx = 0; kx < 5; kx++) {
                    unsigned long long vp = pk2(ip[kx], ip[kx]);
                    const ulonglong2* wq = (const ulonglong2*)(s_w + tap0 + kx * 8);
                    ulonglong2 wA = wq[0], wB = wq[1];
                    fma2(acc[0], vp, wA.x); fma2(acc[1], vp, wA.y);
                    fma2(acc[2], vp, wB.x); fma2(acc[3], vp, wB.y);
                }
            }
#pragma unroll
        for (int o2 = 0; o2 < 4; o2++) {
            float2 p = upk(acc[o2]);
            int o = o2 * 2;
            float v0 = p.x + bias[ocb + o];
            float v1 = p.y + bias[ocb + o + 1];
            s_ch[o * 324 + tid]       = v0;
            s_ch[(o + 1) * 324 + tid] = v1;
            g_h1[(b * 16 + ocb + o) * HW1 + tid]     = v0;
            g_h1[(b * 16 + ocb + o + 1) * HW1 + tid] = v1;
        }
    }
    __syncthreads();

    for (int job = tid; job < 8 * 196; job += 352) {
        int c = job / 196;
        int p = job - c * 196;
        int py = p / 14, px = p - py * 14;
        s_ep[job] = patch_entropy(s_ch + c * 324 + py * 18 + px, s_e);
    }
    __syncthreads();

    int lane = tid & 31, wid = tid >> 5;
    for (int c = wid; c < 8; c += 11) {
        float e = 0.f;
        for (int i = lane; i < 196; i += 32) e += s_ep[c * 196 + i];
        float s = 0.f, q = 0.f;
        for (int i = lane; i < 324; i += 32) {
            float v = s_ch[c * 324 + i];
            s += v; q = fmaf(v, v, q);
        }
#pragma unroll
        for (int o = 16; o > 0; o >>= 1) {
            e += __shfl_down_sync(0xffffffffu, e, o);
            s += __shfl_down_sync(0xffffffffu, s, o);
            q += __shfl_down_sync(0xffffffffu, q, o);
        }
        if (lane == 0) {
            float ent = e * (1.0f / 196.0f);
            float mu = s * (1.0f / 324.0f);
            float var = (q * (1.0f / 324.0f) - mu * mu) * (324.0f / 323.0f);
            float a = rsqrtf(var + EPSN) * nw[ocb + c] * ent;
            g_a1[b * 16 + ocb + c] = a;
            g_b1[b * 16 + ocb + c] = nb[ocb + c] - mu * a;
        }
    }
}

// ---------------- K4: conv2 3x3 s1 p1 + fused entropy/instance-norm stats ----------------
// grid 128 = 64b x 2 halves (16 oc each), block 352.
// dyn smem: s_in 6400 | s_w 2304 | s_ch 5184 | s_ep 3136
__global__ void k_conv2ent(const float* __restrict__ w, const float* __restrict__ bias,
                           const float* __restrict__ nw, const float* __restrict__ nb) {
    extern __shared__ float sm[];
    float* s_in = sm;
    float* s_w  = sm + 6400;
    float* s_ch = sm + 6400 + 2304;
    float* s_ep = sm + 6400 + 2304 + 5184;
    __shared__ float s_a[16], s_b[16];
    __shared__ float s_e[26];
    int b = blockIdx.x >> 1, ocb = (blockIdx.x & 1) * 16;
    int tid = threadIdx.x;

    if (tid < 16) { s_a[tid] = g_a1[b * 16 + tid]; s_b[tid] = g_b1[b * 16 + tid]; }
    if (tid >= 32 && tid < 58) s_e[tid - 32] = g_lut[tid - 32];
    for (int i = tid; i < 2304; i += 352) {
        int o = i / 144, rem = i - o * 144;
        s_w[rem * 16 + o] = w[(ocb + o) * 144 + rem];
    }
    __syncthreads();

    for (int i = tid; i < 6400; i += 352) {
        int ic = i / 400;
        int rem = i - ic * 400;
        int rr = rem / 20, cc = rem - rr * 20;
        int gr = rr - 1, gc = cc - 1;
        float v = 0.f;
        if (gr >= 0 && gr < 18 && gc >= 0 && gc < 18)
            v = fmaxf(fmaf(g_h1[(b * 16 + ic) * 324 + gr * 18 + gc], s_a[ic], s_b[ic]), 0.f);
        s_in[i] = v;
    }
    __syncthreads();

    if (tid < 324) {
        int oy = tid / 18, ox = tid - oy * 18;
        unsigned long long acc[8];
#pragma unroll
        for (int o = 0; o < 8; o++) acc[o] = 0ull;
        for (int ic = 0; ic < 16; ic++)
#pragma unroll
            for (int ky = 0; ky < 3; ky++) {
                const float* ip = s_in + (ic * 20 + oy + ky) * 20 + ox;
                int tap0 = (ic * 9 + ky * 3) * 16;
#pragma unroll
                for (int kx = 0; kx < 3; kx++) {
                    unsigned long long vp = pk2(ip[kx], ip[kx]);
                    const ulonglong2* wq = (const ulonglong2*)(s_w + tap0 + kx * 16);
                    ulonglong2 w0 = wq[0], w1 = wq[1], w2 = wq[2], w3 = wq[3];
                    fma2(acc[0], vp, w0.x); fma2(acc[1], vp, w0.y);
                    fma2(acc[2], vp, w1.x); fma2(acc[3], vp, w1.y);
                    fma2(acc[4], vp, w2.x); fma2(acc[5], vp, w2.y);
                    fma2(acc[6], vp, w3.x); fma2(acc[7], vp, w3.y);
                }
            }
#pragma unroll
        for (int o2 = 0; o2 < 8; o2++) {
            float2 p = upk(acc[o2]);
            int o = o2 * 2;
            float v0 = p.x + bias[ocb + o];
            float v1 = p.y + bias[ocb + o + 1];
            s_ch[o * 324 + tid]       = v0;
            s_ch[(o + 1) * 324 + tid] = v1;
            g_h2[(b * 32 + ocb + o) * 324 + tid]     = v0;
            g_h2[(b * 32 + ocb + o + 1) * 324 + tid] = v1;
        }
    }
    __syncthreads();

    for (int job = tid; job < 16 * 196; job += 352) {
        int c = job / 196;
        int p = job - c * 196;
        int py = p / 14, px = p - py * 14;
        s_ep[job] = patch_entropy(s_ch + c * 324 + py * 18 + px, s_e);
    }
    __syncthreads();

    int lane = tid & 31, wid = tid >> 5;
    for (int c = wid; c < 16; c += 11) {
        float e = 0.f;
        for (int i = lane; i < 196; i += 32) e += s_ep[c * 196 + i];
        float s = 0.f, q = 0.f;
        for (int i = lane; i < 324; i += 32) {
            float v = s_ch[c * 324 + i];
            s += v; q = fmaf(v, v, q);
        }
#pragma unroll
        for (int o = 16; o > 0; o >>= 1) {
            e += __shfl_down_sync(0xffffffffu, e, o);
            s += __shfl_down_sync(0xffffffffu, s, o);
            q += __shfl_down_sync(0xffffffffu, q, o);
        }
        if (lane == 0) {
            float ent = e * (1.0f / 196.0f);
            float mu = s * (1.0f / 324.0f);
            float var = (q * (1.0f / 324.0f) - mu * mu) * (324.0f / 323.0f);
            float a = rsqrtf(var + EPSN) * nw[ocb + c] * ent;
            g_a2[b * 32 + ocb + c] = a;
            g_b2[b * 32 + ocb + c] = nb[ocb + c] - mu * a;
        }
    }
}

// ---------------- K5: fused BN1d + split-K GEMM (deterministic partials) ----------------
// 81 blocks x 128 features, block 256.
// dyn smem: s_h 64x132 | s_w 32x128 | s_rs 256 | s_rq 256 | s_sc 128 | s_sh 128
__global__ void k_gemm(const float* __restrict__ fw, const float* __restrict__ bng,
                       const float* __restrict__ bnb) {
    extern __shared__ float sm[];
    float* s_h  = sm;
    float* s_w  = sm + 64 * 132;
    float* s_rs = s_w + 4096;
    float* s_rq = s_rs + 256;
    float* s_sc = s_rq + 256;
    float* s_sh = s_sc + 128;
    int f0 = blockIdx.x * 128;
    int tid = threadIdx.x;

    for (int i = tid; i < 8192; i += 256) {
        int bb = i >> 7, k = i & 127;
        int f = f0 + k, c = f / 324;
        s_h[bb * 132 + k] =
            fmaxf(fmaf(g_h2[(size_t)bb * F + f], g_a2[bb * 32 + c], g_b2[bb * 32 + c]), 0.f);
    }
    for (int i = tid; i < 4096; i += 256) {
        int j = i >> 7, k = i & 127;
        s_w[j * 128 + k] = fw[(size_t)j * F + f0 + k];
    }
    __syncthreads();

    // BN1d stats over batch (biased), 2 threads per feature
    {
        int k = tid & 127, half = tid >> 7;
        float s = 0.f, q = 0.f;
#pragma unroll 8
        for (int bb = half * 32; bb < half * 32 + 32; bb++) {
            float v = s_h[bb * 132 + k];
            s += v; q = fmaf(v, v, q);
        }
        s_rs[tid] = s; s_rq[tid] = q;
    }
    __syncthreads();
    if (tid < 128) {
        float S = s_rs[tid] + s_rs[tid + 128];
        float Q = s_rq[tid] + s_rq[tid + 128];
        float mu = S * (1.f / 64.f);
        float var = Q * (1.f / 64.f) - mu * mu;
        float sc = bng[f0 + tid] * rsqrtf(var + EPSN);
        s_sc[tid] = sc;
        s_sh[tid] = bnb[f0 + tid] - mu * sc;
    }
    __syncthreads();
    for (int i = tid; i < 8192; i += 256) {
        int bb = i >> 7, k = i & 127;
        s_h[bb * 132 + k] = fmaf(s_h[bb * 132 + k], s_sc[k], s_sh[k]);
    }
    __syncthreads();

    int bb = tid & 63, jg = tid >> 6;
    unsigned long long acc2[8];
#pragma unroll
    for (int j = 0; j < 8; j++) acc2[j] = 0ull;
    const float* hp = s_h + bb * 132;
    const float* wp = s_w + jg * 8 * 128;
    for (int k = 0; k < 128; k += 4) {
        ulonglong2 h2 = *(const ulonglong2*)(hp + k);
#pragma unroll
        for (int j = 0; j < 8; j++) {
            ulonglong2 w2 = *(const ulonglong2*)(wp + j * 128 + k);
            fma2(acc2[j], h2.x, w2.x);
            fma2(acc2[j], h2.y, w2.y);
        }
    }
#pragma unroll
    for (int j = 0; j < 8; j++) {
        float2 p = upk(acc2[j]);
        g_part[(size_t)blockIdx.x * 2048 + bb * 32 + jg * 8 + j] = p.x + p.y;
    }
}

// ---------------- K6: reduce partials + fc relu + heads + softmax ----------------
__global__ void k_heads(const float* __restrict__ fcb,
                        const float* __restrict__ sw, const float* __restrict__ sb,
                        const float* __restrict__ vw, const float* __restrict__ vb,
                        float* __restrict__ out) {
    __shared__ float s_y[2048];
    int tid = threadIdx.x;
    for (int t = tid; t < 2048; t += 1024) {
        float acc = 0.f;
#pragma unroll 8
        for (int p = 0; p < 81; p++) acc += g_part[(size_t)p * 2048 + t];
        s_y[t] = fmaxf(acc + fcb[t & 31], 0.f);
    }
    __syncthreads();
    if (tid < 64) {
        int b = tid;
        float h[32];
#pragma unroll
        for (int j = 0; j < 32; j++) h[j] = s_y[b * 32 + j];

        float sl[5];
#pragma unroll
        for (int k = 0; k < 5; k++) {
            float a = sb[k];
            for (int j = 0; j < 32; j++) a = fmaf(h[j], sw[k * 32 + j], a);
            sl[k] = a;
        }
        float mx = sl[0];
#pragma unroll
        for (int k = 1; k < 5; k++) mx = fmaxf(mx, sl[k]);
        float den = 0.f;
#pragma unroll
        for (int k = 0; k < 5; k++) { sl[k] = expf(sl[k] - mx); den += sl[k]; }
        float invd = 1.f / den;
#pragma unroll
        for (int k = 0; k < 5; k++) out[b * 5 + k] = sl[k] * invd;

        float vl[2];
#pragma unroll
        for (int k = 0; k < 2; k++) {
            float a = vb[k];
            for (int j = 0; j < 32; j++) a = fmaf(h[j], vw[k * 32 + j], a);
            vl[k] = a;
        }
        float m2 = fmaxf(vl[0], vl[1]);
        float e0 = expf(vl[0] - m2), e1 = expf(vl[1] - m2);
        float id = 1.f / (e0 + e1);
        out[320 + b * 2 + 0] = e0 * id;
        out[320 + b * 2 + 1] = e1 * id;
    }
}

extern "C" void kernel_launch(void* const* d_in, const int* in_sizes, int n_in,
                              void* d_out, int out_size) {
    const float* x       = (const float*)d_in[0];
    const float* conv0_w = (const float*)d_in[1];
    const float* conv0_b = (const float*)d_in[2];
    const float* conv1_w = (const float*)d_in[3];
    const float* conv1_b = (const float*)d_in[4];
    const float* conv2_w = (const float*)d_in[5];
    const float* conv2_b = (const float*)d_in[6];
    const float* gn0_w   = (const float*)d_in[7];
    const float* gn0_b   = (const float*)d_in[8];
    const float* n1_w    = (const float*)d_in[9];
    const float* n1_b    = (const float*)d_in[10];
    const float* n2_w    = (const float*)d_in[11];
    const float* n2_b    = (const float*)d_in[12];
    const float* bn_g    = (const float*)d_in[13];
    const float* bn_b    = (const float*)d_in[14];
    const float* fc1_w   = (const float*)d_in[15];
    const float* fc1_b   = (const float*)d_in[16];
    const float* shape_w = (const float*)d_in[17];
    const float* shape_b = (const float*)d_in[18];
    const float* vern_w  = (const float*)d_in[19];
    const float* vern_b  = (const float*)d_in[20];
    float* out = (float*)d_out;

    const int smem0 = (23940 + 1176) * 4;
    const int smem1 = (25088 + 1600 + 2592 + 1568) * 4;
    const int smem2 = (6400 + 2304 + 5184 + 3136) * 4;
    const int smemg = (64 * 132 + 4096 + 256 + 256 + 128 + 128) * 4;
    cudaFuncSetAttribute(k_conv0,    cudaFuncAttributeMaxDynamicSharedMemorySize, smem0);
    cudaFuncSetAttribute(k_conv1ent, cudaFuncAttributeMaxDynamicSharedMemorySize, smem1);
    cudaFuncSetAttribute(k_conv2ent, cudaFuncAttributeMaxDynamicSharedMemorySize, smem2);
    cudaFuncSetAttribute(k_gemm,     cudaFuncAttributeMaxDynamicSharedMemorySize, smemg);

    k_conv0<<<64 * 7, 224, smem0>>>(x, conv0_w, conv0_b);
    k_stats0<<<64 * 8, 256>>>(gn0_w, gn0_b);
    k_conv1ent<<<128, 352, smem1>>>(conv1_w, conv1_b, n1_w, n1_b);
    k_conv2ent<<<128, 352, smem2>>>(conv2_w, conv2_b, n2_w, n2_b);
    k_gemm<<<81, 256, smemg>>>(fc1_w, bn_g, bn_b);
    k_heads<<<1, 1024>>>(fc1_b, shape_w, shape_b, vern_w, vern_b, out);
}